// round 10
// baseline (speedup 1.0000x reference)
#include <cuda_runtime.h>

// PSF patch renderer, binned-tile design (output written EXACTLY once):
//   K0: zero 4096 per-(image,tile) counters.
//   K1: 131072 threads; each point -> the 1..4 tiles its 6x6 patch overlaps
//       (global atomicAdd on counter + float2 store into bin).
//   K2: one CTA per 64x128 tile; reads only its ~36 points, renders the ERF
//       patches into a smem tile (smem atomics), writes the tile coalesced.
//       The writeback doubles as the zero-fill -> no 128MB pre-zero pass and
//       no global-atomic read-modify-write DRAM traffic (round-6's two costs).

#define NXC 512
#define NYC 512
#define PHW 3
#define PP  6
#define BB  128
#define SS  1024
#define TR  64          // tile rows
#define TC  128         // tile cols
#define TX  (NXC / TR)  // 8 row-tiles
#define TY  (NYC / TC)  // 4 col-tiles
#define NCELL (BB * TX * TY)   // 4096
#define CAP 128

__device__ int    g_cnt[NCELL];
__device__ float2 g_bin[NCELL * CAP];

__global__ __launch_bounds__(256)
void zero_counters(void) {
    g_cnt[blockIdx.x * 256 + threadIdx.x] = 0;
}

__global__ __launch_bounds__(256)
void bin_kernel(const float* __restrict__ z) {
    const int b = blockIdx.y;
    const int p = blockIdx.x * 256 + threadIdx.x;   // 0..1023

    const float x0 = z[b * (2 * SS) + p];
    const float y0 = z[b * (2 * SS) + SS + p];
    const int px = __float2int_rn(x0) - PHW;        // jnp.round = rn (half-even)
    const int py = __float2int_rn(y0) - PHW;
    if (px < 0 || px >= NXC - PP || py < 0 || py >= NYC - PP)
        return;                                     // invalid -> contributes zero

    const int t0 = px >> 6, t1 = (px + PP - 1) >> 6;        // row-tile range
    const int u0 = py >> 7, u1 = (py + PP - 1) >> 7;        // col-tile range
    for (int t = t0; t <= t1; t++) {
        for (int u = u0; u <= u1; u++) {
            const int cell = (b * TX + t) * TY + u;
            const int i = atomicAdd(&g_cnt[cell], 1);
            if (i < CAP) g_bin[cell * CAP + i] = make_float2(x0, y0);
        }
    }
}

__global__ __launch_bounds__(256)
void tile_kernel(float* __restrict__ out) {
    __shared__ float tile[TR * TC];                 // 32 KB

    const int b   = blockIdx.y;
    const int tx  = blockIdx.x >> 2;                // 0..7
    const int ty  = blockIdx.x & 3;                 // 0..3
    const int r0  = tx * TR;
    const int c0  = ty * TC;
    const int tid = threadIdx.x;

    float4* t4 = reinterpret_cast<float4*>(tile);
    const float4 zero4 = make_float4(0.f, 0.f, 0.f, 0.f);
    #pragma unroll
    for (int i = 0; i < (TR * TC / 4) / 256; i++)   // 8 iters
        t4[tid + i * 256] = zero4;
    __syncthreads();

    const int cell = (b * TX + tx) * TY + ty;
    const int n = min(g_cnt[cell], CAP);
    const float inv_alpha = 1.0f / (1.41421356237309515f * 0.92f);  // 1/(sqrt2*sigma)

    for (int p = tid; p < n; p += 256) {
        const float2 pt = g_bin[cell * CAP + p];
        const float x0 = pt.x, y0 = pt.y;
        const int px = __float2int_rn(x0) - PHW;
        const int py = __float2int_rn(y0) - PHW;
        const float x0p = x0 - (float)px;
        const float y0p = y0 - (float)py;

        float ex[PP + 1], ey[PP + 1];
        #pragma unroll
        for (int k = 0; k <= PP; k++) {
            const float bk = (float)k - 0.5f;
            ex[k] = erff((bk - x0p) * inv_alpha);
            ey[k] = erff((bk - y0p) * inv_alpha);
        }
        float lx[PP], ly[PP];
        #pragma unroll
        for (int k = 0; k < PP; k++) {
            lx[k] = 500.0f * (ex[k + 1] - ex[k]);   // i0=1000 folded with the 0.5
            ly[k] = 0.5f   * (ey[k + 1] - ey[k]);
        }

        #pragma unroll
        for (int i = 0; i < PP; i++) {
            const int r = px + i - r0;
            if ((unsigned)r >= TR) continue;        // clip to this tile
            const float lxi = lx[i];
            float* trow = tile + r * TC;
            #pragma unroll
            for (int j = 0; j < PP; j++) {
                const int c = py + j - c0;
                if ((unsigned)c >= TC) continue;
                atomicAdd(trow + c, lxi * ly[j]);
            }
        }
    }
    __syncthreads();

    // Coalesced writeback -- this is the only touch of the output (also zeros).
    float* gbase = out + (size_t)b * (NXC * NYC) + (size_t)r0 * NYC + c0;
    #pragma unroll
    for (int i = 0; i < (TR * TC / 4) / 256; i++) { // 8 iters
        const int idx = tid + i * 256;              // float4 index 0..2047
        const int r   = idx >> 5;                   // 32 float4 per row
        const int c4  = idx & 31;
        reinterpret_cast<float4*>(gbase + (size_t)r * NYC)[c4] = t4[idx];
    }
}

extern "C" void kernel_launch(void* const* d_in, const int* in_sizes, int n_in,
                              void* d_out, int out_size) {
    const float* z = (const float*)d_in[0];
    float* out = (float*)d_out;
    zero_counters<<<NCELL / 256, 256>>>();
    bin_kernel<<<dim3(SS / 256, BB), 256>>>(z);
    tile_kernel<<<dim3(TX * TY, BB), 256>>>(out);
}

// round 17
// speedup vs baseline: 1.3968x; 1.3968x over previous
#include <cuda_runtime.h>
#include <cstdint>

// PSF patch renderer, two-phase:
//   K1 zero_tma: zero via TMA bulk stores. The old STG path was issue-floor
//       bound (8.4M STG.128 / 148 SMs @ ~1/cyc = 26us). Each CTA zeroes a
//       32KB smem buffer once, then 8 one-instruction cp.async.bulk copies
//       write 256KB. Binding constraint becomes LTS/HBM (~16us for 128MB).
//   K2 scatter_kernel: ONE WARP PER POINT. Lanes 0..6 compute the 7 x/y
//       boundary erfs in parallel (shfl-shared). Lane l owns patch element
//       (i,j)=(l/6,l%6): row-contiguous addresses -> whole 6x6 patch in
//       2 RED.32 instrs (~9 L1tex wavefronts vs ~32x24 thread-per-point).

#define NXC 512
#define NYC 512
#define PHW 3
#define PP  6
#define BB  128
#define SS  1024

#define ZCHUNK 32768           // 32KB smem buffer
#define ZCOPIES 8              // per CTA -> 256KB per CTA
#define ZCTAS  512             // 512 * 256KB = 128MB

__global__ __launch_bounds__(128)
void zero_tma(float* __restrict__ out) {
    __shared__ __align__(16) float4 buf[ZCHUNK / 16];   // 32KB

    const int tid = threadIdx.x;
    const float4 z4 = make_float4(0.f, 0.f, 0.f, 0.f);
    #pragma unroll
    for (int i = 0; i < (ZCHUNK / 16) / 128; i++)       // 16 iters
        buf[tid + i * 128] = z4;
    __syncthreads();

    if (tid == 0) {
        uint32_t saddr;
        asm("{ .reg .u64 t; cvta.to.shared.u64 t, %1; cvt.u32.u64 %0, t; }"
            : "=r"(saddr) : "l"(buf));
        // generic->async proxy ordering for the smem zeros
        asm volatile("fence.proxy.async.shared::cta;" ::: "memory");

        char* gbase = reinterpret_cast<char*>(out) +
                      (size_t)blockIdx.x * (ZCHUNK * ZCOPIES);
        #pragma unroll
        for (int k = 0; k < ZCOPIES; k++) {
            asm volatile(
                "cp.async.bulk.global.shared::cta.bulk_group [%0], [%1], %2;"
                :: "l"(gbase + (size_t)k * ZCHUNK), "r"(saddr), "n"(ZCHUNK)
                : "memory");
        }
        asm volatile("cp.async.bulk.commit_group;" ::: "memory");
        asm volatile("cp.async.bulk.wait_group 0;" ::: "memory");
    }
}

__device__ __forceinline__ void red1(float* p, float v) {
    asm volatile("red.global.add.f32 [%0], %1;" :: "l"(p), "f"(v) : "memory");
}

__global__ __launch_bounds__(256)
void scatter_kernel(const float* __restrict__ z, float* __restrict__ out) {
    // one warp per point: 131072 warps = 16384 blocks x 8 warps
    const int gw   = blockIdx.x * 8 + (threadIdx.x >> 5);
    const int lane = threadIdx.x & 31;
    const int b    = gw >> 10;          // image
    const int p    = gw & 1023;         // point

    const float x0 = z[b * (2 * SS) + p];
    const float y0 = z[b * (2 * SS) + SS + p];

    const int px = __float2int_rn(x0) - PHW;   // jnp.round = rn (half-even)
    const int py = __float2int_rn(y0) - PHW;
    if (px < 0 || px >= NXC - PP || py < 0 || py >= NYC - PP)
        return;                          // warp-uniform -> no divergence

    const float x0p = x0 - (float)px;
    const float y0p = y0 - (float)py;
    const float ia  = 1.0f / (1.41421356237309515f * 0.92f);  // 1/(sqrt2*sigma)

    // lanes 0..6 hold boundary erfs ex_k, ey_k (k = lane)
    const float bk  = (float)lane - 0.5f;
    const float exv = erff((bk - x0p) * ia);
    const float eyv = erff((bk - y0p) * ia);

    float* img = out + (size_t)b * (NXC * NYC);

    {   // elements l = 0..31
        const int i = lane / 6;
        const int j = lane - 6 * i;
        const float lx = 500.0f * (__shfl_sync(0xffffffffu, exv, i + 1) -
                                   __shfl_sync(0xffffffffu, exv, i));
        const float ly = 0.5f   * (__shfl_sync(0xffffffffu, eyv, j + 1) -
                                   __shfl_sync(0xffffffffu, eyv, j));
        red1(img + (px + i) * NYC + (py + j), lx * ly);
    }
    {   // elements l = 32..35 (i=5, j=2..5) on lanes 0..3
        const int j = lane + 2;
        const float lx = 500.0f * (__shfl_sync(0xffffffffu, exv, 6) -
                                   __shfl_sync(0xffffffffu, exv, 5));
        const float ly = 0.5f   * (__shfl_sync(0xffffffffu, eyv,
                                               (lane < 4) ? j + 1 : 6) -
                                   __shfl_sync(0xffffffffu, eyv,
                                               (lane < 4) ? j : 5));
        if (lane < 4)
            red1(img + (px + 5) * NYC + (py + j), lx * ly);
    }
}

extern "C" void kernel_launch(void* const* d_in, const int* in_sizes, int n_in,
                              void* d_out, int out_size) {
    const float* z = (const float*)d_in[0];
    float* out = (float*)d_out;
    zero_tma<<<ZCTAS, 128>>>(out);
    scatter_kernel<<<16384, 256>>>(z, out);
}